// round 16
// baseline (speedup 1.0000x reference)
#include <cuda_runtime.h>
#include <math.h>

#define B_    32
#define N_    51
#define F_    4
#define P_    137
#define E_    408
#define EMB_  32
#define NF_   (N_ * F_)      // 204
#define ROW_  (N_ * EMB_)    // 1632
#define CH_   9              // P chunks
#define PC_   16             // p slots per chunk (zero-padded beyond pc)
#define Q_    8              // p-pairs per chunk
#define CW_   52             // C row stride (ints)

// Static device scratch
__device__ float g_part[(size_t)CH_ * B_ * ROW_];   // 2.09 MB partial accumulators
__device__ int   g_count[B_];                        // zero-init; reset each replay

typedef unsigned long long ull;

__device__ __forceinline__ float htanh(float x) {
    float r;
    asm("tanh.approx.f32 %0, %1;" : "=f"(r) : "f"(x));
    return r;
}
__device__ __forceinline__ ull pk(float lo, float hi) {
    ull r;
    asm("mov.b64 %0, {%1, %2};" : "=l"(r) : "f"(lo), "f"(hi));
    return r;
}
__device__ __forceinline__ void upk(float& lo, float& hi, ull v) {
    asm("mov.b64 {%0, %1}, %2;" : "=f"(lo), "=f"(hi) : "l"(v));
}
__device__ __forceinline__ ull fma2(ull a, ull b, ull c) {
    ull d;
    asm("fma.rn.f32x2 %0, %1, %2, %3;" : "=l"(d) : "l"(a), "l"(b), "l"(c));
    return d;
}
__device__ __forceinline__ int atom_add_acqrel(int* p, int v) {
    int old;
    asm volatile("atom.add.acq_rel.gpu.s32 %0, [%1], %2;"
                 : "=r"(old) : "l"(p), "r"(v) : "memory");
    return old;
}

// ---------------------------------------------------------------------------
// Single fused kernel, 256 threads, grid B*CH. Early cheap zero-barrier, then
// ONE merged setup phase (edges+atomics | x tile | weights | softmax), then
// ballot-scan aggregation (dual acc chains), f32x2 transform, fused MLP tail.
// ---------------------------------------------------------------------------
__global__ __launch_bounds__(256, 2) void main_kernel(
    const float* __restrict__ x,   const int* __restrict__ ei,
    const float* __restrict__ czw, const float* __restrict__ czb,
    const float* __restrict__ chw, const float* __restrict__ chb,
    const float* __restrict__ lzw, const float* __restrict__ lzb,
    const float* __restrict__ lhw, const float* __restrict__ lhb,
    const float* __restrict__ att,
    const float* __restrict__ l1w, const float* __restrict__ l1b,
    const float* __restrict__ l2w, const float* __restrict__ l2b,
    const float* __restrict__ l3w, const float* __restrict__ l3b,
    float* __restrict__ out)
{
    __shared__ ull    xt2  [NF_ * Q_];    // [nf][q] packed (p,p+1); zero-padded
    __shared__ ull    aggs2[N_ * F_ * Q_];
    __shared__ int    s_C[N_ * CW_];      // dense edge-count matrix [dst][src]
    __shared__ int    s_deg[64];          // padded (lanes probe up to 63)
    __shared__ float  s_wz[F_ * EMB_], s_wh[F_ * EMB_];
    __shared__ float  s_bz[EMB_], s_bh[EMB_];
    __shared__ float  s_probs[PC_];       // 0.5*softmax, zero-padded
    __shared__ float  s_ssum[N_ + 1];
    __shared__ int    s_last;

    const int tid = threadIdx.x, lane = tid & 31, w = tid >> 5;   // 8 warps
    const int c  = blockIdx.x % CH_;
    const int b  = blockIdx.x / CH_;
    const int p0 = c * PC_;
    const int pc = min(PC_, P_ - p0);     // 16, or 9 for c == 8

    // ---- P0a: issue edge loads early (latency overlaps the zero-barrier) ----
    int es0 = -1, ed0 = 0, es1 = -1, ed1 = 0;
    if (tid < E_)       { es0 = ei[tid];       ed0 = ei[E_ + tid]; }
    if (tid + 256 < E_) { es1 = ei[tid + 256]; ed1 = ei[E_ + tid + 256]; }

    {   // zero C (int4) and deg — the ONLY work before the cheap barrier
        int4* c4 = (int4*)s_C;
        for (int i = tid; i < (N_ * CW_) / 4; i += 256) c4[i] = make_int4(0, 0, 0, 0);
        if (tid < 64) s_deg[tid] = 0;
    }
    __syncthreads();   // cheap: everyone arrives after ~3 stores

    // ---- P0b: merged long phase — atomics | x tile | weights | softmax ----
    if (es0 >= 0) { atomicAdd(&s_C[ed0 * CW_ + es0], 1); atomicAdd(&s_deg[ed0], 1); }
    if (es1 >= 0) { atomicAdd(&s_C[ed1 * CW_ + es1], 1); atomicAdd(&s_deg[ed1], 1); }
    if (tid < N_) atomicAdd(&s_C[tid * CW_ + tid], 1);   // self loop

    {   // x tile, p innermost, zero-padded
        const float* xb = x + (size_t)b * NF_ * P_ + p0;
        float* xtf = (float*)xt2;
        for (int i = tid; i < NF_ * PC_; i += 256) {
            int r = i >> 4, p = i & 15;
            xtf[i] = (p < pc) ? xb[r * P_ + p] : 0.f;
        }
    }

    // softmax (warp 1; s_probs read only after the next barrier)
    if (w == 1) {
        float areg[5];
        #pragma unroll
        for (int i = 0; i < 5; i++) {
            int p = lane + 32 * i;
            areg[i] = (p < P_) ? att[p] : -1e30f;
        }
        float mx = -1e30f;
        #pragma unroll
        for (int i = 0; i < 5; i++) mx = fmaxf(mx, areg[i]);
        #pragma unroll
        for (int o = 16; o; o >>= 1) mx = fmaxf(mx, __shfl_xor_sync(0xffffffffu, mx, o));
        float s = 0.f;
        #pragma unroll
        for (int i = 0; i < 5; i++) s += __expf(areg[i] - mx);   // padding -> 0
        #pragma unroll
        for (int o = 16; o; o >>= 1) s += __shfl_xor_sync(0xffffffffu, s, o);
        float inv = 0.5f / s;                 // fold the 0.5 gate factor
        if (lane < PC_)
            s_probs[lane] = (lane < pc) ? __expf(att[p0 + lane] - mx) * inv : 0.f;
    }

    // composed weights: wz' = 0.5*(czw@lzw) (tanh half-arg), wh' = chw@lhw
    if (tid < 128) {
        int f = tid >> 5, e = tid & 31;
        float a = 0.f;
        #pragma unroll
        for (int k = 0; k < EMB_; k++) a += czw[f * EMB_ + k] * lzw[k * EMB_ + e];
        s_wz[tid] = a * 0.5f;
        if (f == 0) {
            float bb = lzb[e];
            #pragma unroll
            for (int k = 0; k < EMB_; k++) bb += czb[k] * lzw[k * EMB_ + e];
            s_bz[e] = bb * 0.5f;
        }
    } else {
        int t = tid - 128, f = t >> 5, e = t & 31;
        float a = 0.f;
        #pragma unroll
        for (int k = 0; k < EMB_; k++) a += chw[f * EMB_ + k] * lhw[k * EMB_ + e];
        s_wh[t] = a;
        if (f == 0) {
            float bb = lhb[e];
            #pragma unroll
            for (int k = 0; k < EMB_; k++) bb += chb[k] * lhw[k * EMB_ + e];
            s_bh[e] = bb;
        }
    }
    __syncthreads();

    // ---- P4: ballot-scan aggregation, dual acc chains; warp w owns w,w+8,.. ----
    #pragma unroll 1
    for (int k = 0; k < 7; k++) {
        int n = w + 8 * k;
        if (n >= N_) break;                    // uniform per warp
        float rsn = rsqrtf((float)(s_deg[n] + 1));
        int c1 = s_C[n * CW_ + lane];
        int m2 = 32 + lane;
        int c2 = (m2 < N_) ? s_C[n * CW_ + m2] : 0;
        unsigned msk1 = __ballot_sync(0xffffffffu, c1 != 0);
        unsigned msk2 = __ballot_sync(0xffffffffu, c2 != 0);
        float wt1 = (float)c1 * rsn * rsqrtf((float)(s_deg[lane] + 1));
        float wt2 = (float)c2 * rsn * rsqrtf((float)(s_deg[m2] + 1));
        ull accA = 0, accB = 0;                // two independent chains
        while (msk1) {
            int m = __ffs(msk1) - 1; msk1 &= msk1 - 1;
            float wt = __shfl_sync(0xffffffffu, wt1, m);
            accA = fma2(pk(wt, wt), xt2[m * 32 + lane], accA);
            if (msk1) {
                int m3 = __ffs(msk1) - 1; msk1 &= msk1 - 1;
                float wt3 = __shfl_sync(0xffffffffu, wt1, m3);
                accB = fma2(pk(wt3, wt3), xt2[m3 * 32 + lane], accB);
            }
        }
        while (msk2) {
            int m = __ffs(msk2) - 1; msk2 &= msk2 - 1;
            float wt = __shfl_sync(0xffffffffu, wt2, m);
            accA = fma2(pk(wt, wt), xt2[(32 + m) * 32 + lane], accA);
            if (msk2) {
                int m3 = __ffs(msk2) - 1; msk2 &= msk2 - 1;
                float wt3 = __shfl_sync(0xffffffffu, wt2, m3);
                accB = fma2(pk(wt3, wt3), xt2[(32 + m3) * 32 + lane], accB);
            }
        }
        float aLo, aHi, bLo, bHi;
        upk(aLo, aHi, accA); upk(bLo, bHi, accB);
        aggs2[n * 32 + lane] = pk(aLo + bLo, aHi + bHi);   // lane = f*8+q channel
    }
    __syncwarp();   // warp w consumes only its own nodes below

    // ---- P5: f32x2 4->32 transform + gated activation over p-pairs ----
    ull wz2[F_], wh2[F_];
    #pragma unroll
    for (int f = 0; f < F_; f++) {
        float vz = s_wz[f * EMB_ + lane], vh = s_wh[f * EMB_ + lane];
        wz2[f] = pk(vz, vz); wh2[f] = pk(vh, vh);
    }
    const float bzr = s_bz[lane], bhr = s_bh[lane];
    const ull bz2 = pk(bzr, bzr), bh2 = pk(bhr, bhr);

    ull acc2[7];
    #pragma unroll
    for (int k = 0; k < 7; k++) acc2[k] = pk(0.f, 0.f);

    #pragma unroll 2
    for (int q = 0; q < Q_; q++) {
        const float prl = s_probs[2 * q], prh = s_probs[2 * q + 1];
        const ull pr2  = pk(prl, prh);
        const ull npr2 = pk(-prl, -prh);
        #pragma unroll
        for (int k = 0; k < 7; k++) {
            int n = w + 8 * k;
            if (n >= N_) break;
            const ull* av = &aggs2[n * (F_ * Q_) + q];   // broadcast LDS.64 x4
            ull ax = av[0 * Q_], ay = av[1 * Q_], az = av[2 * Q_], aw = av[3 * Q_];
            ull zh = fma2(ax, wz2[0], bz2);
            zh = fma2(ay, wz2[1], zh); zh = fma2(az, wz2[2], zh); zh = fma2(aw, wz2[3], zh);
            ull hh = fma2(ax, wh2[0], bh2);
            hh = fma2(ay, wh2[1], hh); hh = fma2(az, wh2[2], hh); hh = fma2(aw, wh2[3], hh);
            float z0, z1, h0, h1;
            upk(z0, z1, zh); upk(h0, h1, hh);
            ull t1 = pk(htanh(z0), htanh(z1));
            ull t2 = pk(htanh(h0), htanh(h1));
            ull tmp = fma2(t1, npr2, pr2);      // (pr2 - pr2*t1) per half
            acc2[k] = fma2(tmp, t2, acc2[k]);   // padded p contributes exactly 0
        }
    }

    float* op = g_part + (size_t)(c * B_ + b) * ROW_;
    #pragma unroll
    for (int k = 0; k < 7; k++) {
        int i = tid + 256 * k;                // = (w+8k)*32 + lane
        if (i < ROW_) {
            float lo, hi;
            upk(lo, hi, acc2[k]);
            op[i] = lo + hi;
        }
    }

    // ---- Tail: last-arriving block per b runs the MLP head ----
    if (tid == 0) {
        int old = atom_add_acqrel(&g_count[b], 1);
        s_last = (old == CH_ - 1) ? 1 : 0;
    }
    __syncthreads();
    if (!s_last) return;

    float* sh = (float*)aggs2;   // 1632 floats
    float* w1 = (float*)xt2;     // 1024 floats

    for (int i = tid; i < ROW_ / 4; i += 256) {
        const float4* gp = (const float4*)(g_part + (size_t)b * ROW_) + i;
        const size_t stride4 = (size_t)B_ * ROW_ / 4;
        float4 s = make_float4(0.f, 0.f, 0.f, 0.f);
        #pragma unroll
        for (int cc = 0; cc < CH_; cc++) {
            float4 v = gp[cc * stride4];
            s.x += v.x; s.y += v.y; s.z += v.z; s.w += v.w;
        }
        ((float4*)sh)[i] = make_float4(fmaxf(s.x, 0.f), fmaxf(s.y, 0.f),
                                       fmaxf(s.z, 0.f), fmaxf(s.w, 0.f));
    }
    for (int i = tid; i < EMB_ * 32; i += 256) w1[i] = l1w[i];
    __syncthreads();

    const float w2j = l2w[lane];
    const float b1j = l1b[lane];
    for (int idx = tid; idx < N_ * 32; idx += 256) {
        int n = idx >> 5;                  // idx&31 == lane
        float a = b1j;
        #pragma unroll
        for (int e = 0; e < EMB_; e++) a += sh[n * EMB_ + e] * w1[e * 32 + lane];
        a = fmaxf(a, 0.f) * w2j;
        #pragma unroll
        for (int o = 16; o; o >>= 1) a += __shfl_xor_sync(0xffffffffu, a, o);
        if (lane == 0) s_ssum[n] = a;
    }
    __syncthreads();

    if (tid < 32) {
        float v = 0.f;
        const float b2 = l2b[0];
        for (int n = lane; n < N_; n += 32) v += (s_ssum[n] + b2) * l3w[n];
        #pragma unroll
        for (int o = 16; o; o >>= 1) v += __shfl_xor_sync(0xffffffffu, v, o);
        if (lane == 0) {
            out[b] = 1.f / (1.f + __expf(-(v + l3b[0])));
            g_count[b] = 0;                // reset for next graph replay
        }
    }
}

// ---------------------------------------------------------------------------
extern "C" void kernel_launch(void* const* d_in, const int* in_sizes, int n_in,
                              void* d_out, int out_size) {
    const float* x   = (const float*)d_in[0];
    const int*   ei  = (const int*)  d_in[1];
    const float* czw = (const float*)d_in[2];
    const float* czb = (const float*)d_in[3];
    // d_in[4..5]: conv_r_* unused (R gate multiplies H == 0)
    const float* chw = (const float*)d_in[6];
    const float* chb = (const float*)d_in[7];
    const float* lzw = (const float*)d_in[8];
    const float* lzb = (const float*)d_in[9];
    // d_in[10..11]: lin_r_* unused
    const float* lhw = (const float*)d_in[12];
    const float* lhb = (const float*)d_in[13];
    const float* att = (const float*)d_in[14];
    const float* l1w = (const float*)d_in[15];
    const float* l1b = (const float*)d_in[16];
    const float* l2w = (const float*)d_in[17];
    const float* l2b = (const float*)d_in[18];
    const float* l3w = (const float*)d_in[19];
    const float* l3b = (const float*)d_in[20];
    float* out = (float*)d_out;

    main_kernel<<<B_ * CH_, 256>>>(x, ei, czw, czb, chw, chb, lzw, lzb, lhw, lhb,
                                   att, l1w, l1b, l2w, l2b, l3w, l3b, out);
}

// round 17
// speedup vs baseline: 1.1066x; 1.1066x over previous
#include <cuda_runtime.h>
#include <math.h>

#define B_    32
#define N_    51
#define F_    4
#define P_    137
#define E_    408
#define EMB_  32
#define NF_   (N_ * F_)      // 204
#define ROW_  (N_ * EMB_)    // 1632
#define CH_   9              // P chunks
#define PC_   16             // p slots per chunk (zero-padded beyond pc)
#define Q_    8              // p-pairs per chunk
#define CW_   52             // C row stride (ints)

// Static device scratch
__device__ float g_part[(size_t)CH_ * B_ * ROW_];   // 2.09 MB partial accumulators
__device__ int   g_count[B_];                        // zero-init; reset each replay

typedef unsigned long long ull;

__device__ __forceinline__ float htanh(float x) {
    float r;
    asm("tanh.approx.f32 %0, %1;" : "=f"(r) : "f"(x));
    return r;
}
__device__ __forceinline__ ull pk(float lo, float hi) {
    ull r;
    asm("mov.b64 %0, {%1, %2};" : "=l"(r) : "f"(lo), "f"(hi));
    return r;
}
__device__ __forceinline__ void upk(float& lo, float& hi, ull v) {
    asm("mov.b64 {%0, %1}, %2;" : "=f"(lo), "=f"(hi) : "l"(v));
}
__device__ __forceinline__ ull fma2(ull a, ull b, ull c) {
    ull d;
    asm("fma.rn.f32x2 %0, %1, %2, %3;" : "=l"(d) : "l"(a), "l"(b), "l"(c));
    return d;
}
__device__ __forceinline__ int atom_add_acqrel(int* p, int v) {
    int old;
    asm volatile("atom.add.acq_rel.gpu.s32 %0, [%1], %2;"
                 : "=r"(old) : "l"(p), "r"(v) : "memory");
    return old;
}

// ---------------------------------------------------------------------------
// Single fused kernel, 256 threads, grid B*CH (R14 structure — best known).
// P0 overlaps edge-load latency with x tile + weight comp + softmax; P1 does
// the (now data-ready) count-matrix atomics; ballot-scan aggregation; f32x2
// transform; fused MLP tail on the last-arriving block per b.
// ---------------------------------------------------------------------------
__global__ __launch_bounds__(256, 2) void main_kernel(
    const float* __restrict__ x,   const int* __restrict__ ei,
    const float* __restrict__ czw, const float* __restrict__ czb,
    const float* __restrict__ chw, const float* __restrict__ chb,
    const float* __restrict__ lzw, const float* __restrict__ lzb,
    const float* __restrict__ lhw, const float* __restrict__ lhb,
    const float* __restrict__ att,
    const float* __restrict__ l1w, const float* __restrict__ l1b,
    const float* __restrict__ l2w, const float* __restrict__ l2b,
    const float* __restrict__ l3w, const float* __restrict__ l3b,
    float* __restrict__ out)
{
    __shared__ ull    xt2  [NF_ * Q_];    // [nf][q] packed (p,p+1); zero-padded
    __shared__ ull    aggs2[N_ * F_ * Q_];
    __shared__ int    s_C[N_ * CW_];      // dense edge-count matrix [dst][src]
    __shared__ int    s_deg[64];          // padded (lanes probe up to 63)
    __shared__ float  s_wz[F_ * EMB_], s_wh[F_ * EMB_];
    __shared__ float  s_bz[EMB_], s_bh[EMB_];
    __shared__ float  s_probs[PC_];       // 0.5*softmax, zero-padded
    __shared__ float  s_ssum[N_ + 1];
    __shared__ int    s_last;

    const int tid = threadIdx.x, lane = tid & 31, w = tid >> 5;   // 8 warps
    const int c  = blockIdx.x % CH_;
    const int b  = blockIdx.x / CH_;
    const int p0 = c * PC_;
    const int pc = min(PC_, P_ - p0);     // 16, or 9 for c == 8

    // ---- P0: all global loads + zeroing + weight comp + softmax ----
    int es0 = -1, ed0 = 0, es1 = -1, ed1 = 0;
    if (tid < E_)       { es0 = ei[tid];       ed0 = ei[E_ + tid]; }
    if (tid + 256 < E_) { es1 = ei[tid + 256]; ed1 = ei[E_ + tid + 256]; }

    {   // zero C (int4) and deg
        int4* c4 = (int4*)s_C;
        for (int i = tid; i < (N_ * CW_) / 4; i += 256) c4[i] = make_int4(0, 0, 0, 0);
        if (tid < 64) s_deg[tid] = 0;
    }

    {   // x tile, p innermost, zero-padded
        const float* xb = x + (size_t)b * NF_ * P_ + p0;
        float* xtf = (float*)xt2;
        for (int i = tid; i < NF_ * PC_; i += 256) {
            int r = i >> 4, p = i & 15;
            xtf[i] = (p < pc) ? xb[r * P_ + p] : 0.f;
        }
    }

    // softmax (warp 1, no smem deps; s_probs read only after next barrier)
    if (w == 1) {
        float areg[5];
        #pragma unroll
        for (int i = 0; i < 5; i++) {
            int p = lane + 32 * i;
            areg[i] = (p < P_) ? att[p] : -1e30f;
        }
        float mx = -1e30f;
        #pragma unroll
        for (int i = 0; i < 5; i++) mx = fmaxf(mx, areg[i]);
        #pragma unroll
        for (int o = 16; o; o >>= 1) mx = fmaxf(mx, __shfl_xor_sync(0xffffffffu, mx, o));
        float s = 0.f;
        #pragma unroll
        for (int i = 0; i < 5; i++) s += __expf(areg[i] - mx);   // padding -> 0
        #pragma unroll
        for (int o = 16; o; o >>= 1) s += __shfl_xor_sync(0xffffffffu, s, o);
        float inv = 0.5f / s;                 // fold the 0.5 gate factor
        if (lane < PC_)
            s_probs[lane] = (lane < pc) ? __expf(att[p0 + lane] - mx) * inv : 0.f;
    }

    // composed weights: wz' = 0.5*(czw@lzw) (tanh half-arg), wh' = chw@lhw
    if (tid < 128) {
        int f = tid >> 5, e = tid & 31;
        float a = 0.f;
        #pragma unroll
        for (int k = 0; k < EMB_; k++) a += czw[f * EMB_ + k] * lzw[k * EMB_ + e];
        s_wz[tid] = a * 0.5f;
        if (f == 0) {
            float bb = lzb[e];
            #pragma unroll
            for (int k = 0; k < EMB_; k++) bb += czb[k] * lzw[k * EMB_ + e];
            s_bz[e] = bb * 0.5f;
        }
    } else {
        int t = tid - 128, f = t >> 5, e = t & 31;
        float a = 0.f;
        #pragma unroll
        for (int k = 0; k < EMB_; k++) a += chw[f * EMB_ + k] * lhw[k * EMB_ + e];
        s_wh[t] = a;
        if (f == 0) {
            float bb = lhb[e];
            #pragma unroll
            for (int k = 0; k < EMB_; k++) bb += chb[k] * lhw[k * EMB_ + e];
            s_bh[e] = bb;
        }
    }
    __syncthreads();

    // ---- P1: edge atomics + self-loop counts (deterministic int adds) ----
    if (es0 >= 0) { atomicAdd(&s_C[ed0 * CW_ + es0], 1); atomicAdd(&s_deg[ed0], 1); }
    if (es1 >= 0) { atomicAdd(&s_C[ed1 * CW_ + es1], 1); atomicAdd(&s_deg[ed1], 1); }
    if (tid < N_) atomicAdd(&s_C[tid * CW_ + tid], 1);   // self loop
    __syncthreads();

    // ---- P4: ballot-scan aggregation; warp w owns nodes w, w+8, ... ----
    #pragma unroll 1
    for (int k = 0; k < 7; k++) {
        int n = w + 8 * k;
        if (n >= N_) break;                    // uniform per warp
        float rsn = rsqrtf((float)(s_deg[n] + 1));
        int c1 = s_C[n * CW_ + lane];
        int m2 = 32 + lane;
        int c2 = (m2 < N_) ? s_C[n * CW_ + m2] : 0;
        unsigned msk1 = __ballot_sync(0xffffffffu, c1 != 0);
        unsigned msk2 = __ballot_sync(0xffffffffu, c2 != 0);
        float wt1 = (float)c1 * rsn * rsqrtf((float)(s_deg[lane] + 1));
        float wt2 = (float)c2 * rsn * rsqrtf((float)(s_deg[m2] + 1));
        ull acc = 0;
        while (msk1) {
            int m = __ffs(msk1) - 1; msk1 &= msk1 - 1;
            float wt = __shfl_sync(0xffffffffu, wt1, m);
            acc = fma2(pk(wt, wt), xt2[m * 32 + lane], acc);
        }
        while (msk2) {
            int m = __ffs(msk2) - 1; msk2 &= msk2 - 1;
            float wt = __shfl_sync(0xffffffffu, wt2, m);
            acc = fma2(pk(wt, wt), xt2[(32 + m) * 32 + lane], acc);
        }
        aggs2[n * 32 + lane] = acc;            // lane = f*8+q channel
    }
    __syncwarp();   // warp w consumes only its own nodes below

    // ---- P5: f32x2 4->32 transform + gated activation over p-pairs ----
    ull wz2[F_], wh2[F_];
    #pragma unroll
    for (int f = 0; f < F_; f++) {
        float vz = s_wz[f * EMB_ + lane], vh = s_wh[f * EMB_ + lane];
        wz2[f] = pk(vz, vz); wh2[f] = pk(vh, vh);
    }
    const float bzr = s_bz[lane], bhr = s_bh[lane];
    const ull bz2 = pk(bzr, bzr), bh2 = pk(bhr, bhr);

    ull acc2[7];
    #pragma unroll
    for (int k = 0; k < 7; k++) acc2[k] = pk(0.f, 0.f);

    #pragma unroll 2
    for (int q = 0; q < Q_; q++) {
        const float prl = s_probs[2 * q], prh = s_probs[2 * q + 1];
        const ull pr2  = pk(prl, prh);
        const ull npr2 = pk(-prl, -prh);
        #pragma unroll
        for (int k = 0; k < 7; k++) {
            int n = w + 8 * k;
            if (n >= N_) break;
            const ull* av = &aggs2[n * (F_ * Q_) + q];   // broadcast LDS.64 x4
            ull ax = av[0 * Q_], ay = av[1 * Q_], az = av[2 * Q_], aw = av[3 * Q_];
            ull zh = fma2(ax, wz2[0], bz2);
            zh = fma2(ay, wz2[1], zh); zh = fma2(az, wz2[2], zh); zh = fma2(aw, wz2[3], zh);
            ull hh = fma2(ax, wh2[0], bh2);
            hh = fma2(ay, wh2[1], hh); hh = fma2(az, wh2[2], hh); hh = fma2(aw, wh2[3], hh);
            float z0, z1, h0, h1;
            upk(z0, z1, zh); upk(h0, h1, hh);
            ull t1 = pk(htanh(z0), htanh(z1));
            ull t2 = pk(htanh(h0), htanh(h1));
            ull tmp = fma2(t1, npr2, pr2);      // (pr2 - pr2*t1) per half
            acc2[k] = fma2(tmp, t2, acc2[k]);   // padded p contributes exactly 0
        }
    }

    float* op = g_part + (size_t)(c * B_ + b) * ROW_;
    #pragma unroll
    for (int k = 0; k < 7; k++) {
        int i = tid + 256 * k;                // = (w+8k)*32 + lane
        if (i < ROW_) {
            float lo, hi;
            upk(lo, hi, acc2[k]);
            op[i] = lo + hi;
        }
    }

    // ---- Tail: last-arriving block per b runs the MLP head ----
    if (tid == 0) {
        int old = atom_add_acqrel(&g_count[b], 1);
        s_last = (old == CH_ - 1) ? 1 : 0;
    }
    __syncthreads();
    if (!s_last) return;

    float* sh = (float*)aggs2;   // 1632 floats
    float* w1 = (float*)xt2;     // 1024 floats

    for (int i = tid; i < ROW_ / 4; i += 256) {
        const float4* gp = (const float4*)(g_part + (size_t)b * ROW_) + i;
        const size_t stride4 = (size_t)B_ * ROW_ / 4;
        float4 s = make_float4(0.f, 0.f, 0.f, 0.f);
        #pragma unroll
        for (int cc = 0; cc < CH_; cc++) {
            float4 v = gp[cc * stride4];
            s.x += v.x; s.y += v.y; s.z += v.z; s.w += v.w;
        }
        ((float4*)sh)[i] = make_float4(fmaxf(s.x, 0.f), fmaxf(s.y, 0.f),
                                       fmaxf(s.z, 0.f), fmaxf(s.w, 0.f));
    }
    for (int i = tid; i < EMB_ * 32; i += 256) w1[i] = l1w[i];
    __syncthreads();

    const float w2j = l2w[lane];
    const float b1j = l1b[lane];
    for (int idx = tid; idx < N_ * 32; idx += 256) {
        int n = idx >> 5;                  // idx&31 == lane
        float a = b1j;
        #pragma unroll
        for (int e = 0; e < EMB_; e++) a += sh[n * EMB_ + e] * w1[e * 32 + lane];
        a = fmaxf(a, 0.f) * w2j;
        #pragma unroll
        for (int o = 16; o; o >>= 1) a += __shfl_xor_sync(0xffffffffu, a, o);
        if (lane == 0) s_ssum[n] = a;
    }
    __syncthreads();

    if (tid < 32) {
        float v = 0.f;
        const float b2 = l2b[0];
        for (int n = lane; n < N_; n += 32) v += (s_ssum[n] + b2) * l3w[n];
        #pragma unroll
        for (int o = 16; o; o >>= 1) v += __shfl_xor_sync(0xffffffffu, v, o);
        if (lane == 0) {
            out[b] = 1.f / (1.f + __expf(-(v + l3b[0])));
            g_count[b] = 0;                // reset for next graph replay
        }
    }
}

// ---------------------------------------------------------------------------
extern "C" void kernel_launch(void* const* d_in, const int* in_sizes, int n_in,
                              void* d_out, int out_size) {
    const float* x   = (const float*)d_in[0];
    const int*   ei  = (const int*)  d_in[1];
    const float* czw = (const float*)d_in[2];
    const float* czb = (const float*)d_in[3];
    // d_in[4..5]: conv_r_* unused (R gate multiplies H == 0)
    const float* chw = (const float*)d_in[6];
    const float* chb = (const float*)d_in[7];
    const float* lzw = (const float*)d_in[8];
    const float* lzb = (const float*)d_in[9];
    // d_in[10..11]: lin_r_* unused
    const float* lhw = (const float*)d_in[12];
    const float* lhb = (const float*)d_in[13];
    const float* att = (const float*)d_in[14];
    const float* l1w = (const float*)d_in[15];
    const float* l1b = (const float*)d_in[16];
    const float* l2w = (const float*)d_in[17];
    const float* l2b = (const float*)d_in[18];
    const float* l3w = (const float*)d_in[19];
    const float* l3b = (const float*)d_in[20];
    float* out = (float*)d_out;

    main_kernel<<<B_ * CH_, 256>>>(x, ei, czw, czb, chw, chb, lzw, lzb, lhw, lhb,
                                   att, l1w, l1b, l2w, l2b, l3w, l3b, out);
}